// round 16
// baseline (speedup 1.0000x reference)
#include <cuda_runtime.h>
#include <cuda.h>
#include <cstdint>

// FWHT n=1024 over x[64,1024,512] f32, single pass.
//
// R16: one-shot CTAs, 3 co-resident per SM. Each CTA: TMA-load its
// 1024x16 tile (64KB) -> mbar wait -> register FWHT (two FWHT_32 phases
// around one swizzled smem transpose) -> STG.cs output. No persistent
// loop: the 3 independent CTAs per SM interleave their load/compute/
// store phases (independent barrier domains), and CLC work-stealing
// refills finished CTAs, whose TMA loads issue immediately.
//
// n = 32*a + b. Phase A: FWHT_32 over a (rows 32a+jt); swizzled smem
// exchange; Phase B: FWHT_32 over b (rows jt*32+b) -> STG.

#define FW_N 1024
#define FW_D 512
#define FW_TW 16                          // tile width in floats (64 B)
#define FW_THREADS 128
#define FW_NTILES (64 * (FW_D / FW_TW))   // 2048
#define FW_TILE_BYTES (FW_N * FW_TW * 4)  // 65536
#define FW_SMEM_BYTES (FW_TILE_BYTES + 128)

// packed butterfly on float4-as-ulonglong2: (a,b) -> (a+b, a-b)
__device__ __forceinline__ void bfly4(ulonglong2& a, ulonglong2& b) {
    unsigned long long sx, sy, dx, dy;
    asm("add.rn.f32x2 %0, %4, %6;\n\t"
        "add.rn.f32x2 %1, %5, %7;\n\t"
        "sub.rn.f32x2 %2, %4, %6;\n\t"
        "sub.rn.f32x2 %3, %5, %7;"
        : "=l"(sx), "=l"(sy), "=l"(dx), "=l"(dy)
        : "l"(a.x), "l"(a.y), "l"(b.x), "l"(b.y));
    a.x = sx; a.y = sy;
    b.x = dx; b.y = dy;
}

__device__ __forceinline__ void mbar_init(uint32_t mbar, uint32_t count) {
    asm volatile("mbarrier.init.shared.b64 [%0], %1;" :: "r"(mbar), "r"(count) : "memory");
}
__device__ __forceinline__ void mbar_expect_tx(uint32_t mbar, uint32_t bytes) {
    asm volatile("mbarrier.arrive.expect_tx.shared.b64 _, [%0], %1;"
                 :: "r"(mbar), "r"(bytes) : "memory");
}
__device__ __forceinline__ void mbar_wait(uint32_t mbar, uint32_t parity) {
    uint32_t done;
    asm volatile("{\n\t.reg .pred p;\n\t"
                 "mbarrier.try_wait.parity.acquire.cta.shared::cta.b64 p, [%1], %2;\n\t"
                 "selp.b32 %0, 1, 0, p;\n\t}"
                 : "=r"(done) : "r"(mbar), "r"(parity) : "memory");
    if (!done) {
        asm volatile("{\n\t.reg .pred P1;\n\t"
                     "WL_%=:\n\t"
                     "mbarrier.try_wait.parity.acquire.cta.shared::cta.b64 P1, [%0], %1, 0x989680;\n\t"
                     "@P1 bra.uni WD_%=;\n\t"
                     "bra.uni WL_%=;\n\t"
                     "WD_%=:\n\t}"
                     :: "r"(mbar), "r"(parity) : "memory");
    }
}

__device__ __forceinline__ void tma_load_tile(const CUtensorMap* tm, uint32_t dst,
                                              uint32_t mbar, uint32_t tile) {
    const int c0 = (int)(tile & 31u) * FW_TW;       // d offset (elements)
    const int r0 = (int)(tile >> 5) * FW_N;         // flattened row offset
#pragma unroll
    for (int q = 0; q < 4; ++q) {
        asm volatile(
            "cp.async.bulk.tensor.2d.shared::cta.global.tile.mbarrier::complete_tx::bytes "
            "[%0], [%1, {%2, %3}], [%4];"
            :: "r"(dst + q * 16384), "l"(tm), "r"(c0), "r"(r0 + q * 256), "r"(mbar)
            : "memory");
    }
}

// ---------------- kernel ----------------

__global__ __launch_bounds__(FW_THREADS, 3)
void fwht1024_oneshot(const __grid_constant__ CUtensorMap tin,
                      float* __restrict__ y) {
    extern __shared__ __align__(1024) unsigned char smem[];
    ulonglong2* buf = reinterpret_cast<ulonglong2*>(smem);   // 16B units

    uint32_t smem_u32;
    asm("{ .reg .u64 t; cvta.to.shared.u64 t, %1; cvt.u32.u64 %0, t; }"
        : "=r"(smem_u32) : "l"(smem));
    const uint32_t mbar = smem_u32 + FW_TILE_BYTES;

    const int tid = threadIdx.x;
    const int dq  = tid & 3;          // float4 column (0..3) within 16-float tile
    const int jt  = tid >> 2;         // 0..31
    const uint32_t jsw = (uint32_t)(jt & 1);
    const uint32_t t   = blockIdx.x;

    // issue the TMA load for this CTA's tile immediately
    if (tid == 0) {
        mbar_init(mbar, 1);
        mbar_expect_tx(mbar, FW_TILE_BYTES);
        tma_load_tile(&tin, smem_u32, mbar, t);
    }
    __syncthreads();            // mbar init visible to all threads
    mbar_wait(mbar, 0);

    ulonglong2 v[32];

    // ---- phase A: rows 32a + jt (linear: slot = row*4 + dq = 128a + tid) --
#pragma unroll
    for (int a = 0; a < 32; ++a)
        v[a] = buf[128 * a + tid];

#pragma unroll
    for (int h = 1; h < 32; h <<= 1) {
#pragma unroll
        for (int a = 0; a < 32; ++a)
            if ((a & h) == 0) bfly4(v[a], v[a | h]);
    }

    // store element (a, b=jt) at slot (a*32 + (jt^(a&1)))*4 + dq
#pragma unroll
    for (int a = 0; a < 32; ++a)
        buf[(a * 32 + (jt ^ (a & 1))) * 4 + dq] = v[a];

    __syncthreads();

    // ---- phase B: element (a=jt, b=i) from slot (jt*32 + (i^jsw))*4 + dq --
    const uint32_t pb = (uint32_t)(jt * 128 + dq);
#pragma unroll
    for (int i = 0; i < 32; ++i)
        v[i] = buf[pb + (((uint32_t)i ^ jsw) << 2)];

#pragma unroll
    for (int h = 1; h < 32; h <<= 1) {
#pragma unroll
        for (int i = 0; i < 32; ++i)
            if ((i & h) == 0) bfly4(v[i], v[i | h]);
    }

    // ---- output: rows n = jt*32 + i, streaming STG.128 (64B per 4 lanes) --
    {
        const uint32_t b  = t >> 5;
        const uint32_t dt = t & 31u;
        float4* __restrict__ yout = reinterpret_cast<float4*>(
            y + (size_t)b * (FW_N * FW_D) + dt * FW_TW + dq * 4);
#pragma unroll
        for (int i = 0; i < 32; ++i) {
            float4 f = *reinterpret_cast<float4*>(&v[i]);
            __stcs(&yout[(size_t)(jt * 32 + i) * (FW_D / 4)], f);
        }
    }
}

// ---------------- host ----------------

typedef CUresult (*EncodeTiledFn)(
    CUtensorMap*, CUtensorMapDataType, cuuint32_t, void*,
    const cuuint64_t*, const cuuint64_t*, const cuuint32_t*, const cuuint32_t*,
    CUtensorMapInterleave, CUtensorMapSwizzle, CUtensorMapL2promotion,
    CUtensorMapFloatOOBfill);

extern "C" void kernel_launch(void* const* d_in, const int* in_sizes, int n_in,
                              void* d_out, int out_size) {
    void* xp = (void*)d_in[0];
    float* yp = (float*)d_out;

    void* fn = nullptr;
    cudaDriverEntryPointQueryResult qr;
    cudaGetDriverEntryPoint("cuTensorMapEncodeTiled", &fn, cudaEnableDefault, &qr);
    EncodeTiledFn encode = (EncodeTiledFn)fn;

    cuuint64_t dims[2]    = {FW_D, (cuuint64_t)64 * FW_N};  // {512, 65536}
    cuuint64_t strides[1] = {FW_D * 4};                     // 2048 B per row
    cuuint32_t box[2]     = {FW_TW, 256};
    cuuint32_t es[2]      = {1, 1};

    CUtensorMap tin;
    encode(&tin, CU_TENSOR_MAP_DATA_TYPE_FLOAT32, 2, xp, dims, strides, box, es,
           CU_TENSOR_MAP_INTERLEAVE_NONE, CU_TENSOR_MAP_SWIZZLE_NONE,
           CU_TENSOR_MAP_L2_PROMOTION_L2_128B, CU_TENSOR_MAP_FLOAT_OOB_FILL_NONE);

    cudaFuncSetAttribute(fwht1024_oneshot,
                         cudaFuncAttributeMaxDynamicSharedMemorySize,
                         FW_SMEM_BYTES);

    fwht1024_oneshot<<<FW_NTILES, FW_THREADS, FW_SMEM_BYTES>>>(tin, yp);
}